// round 8
// baseline (speedup 1.0000x reference)
#include <cuda_runtime.h>
#include <cuda_bf16.h>
#include <cstdint>

// ===========================================================================
// Protein graph featurization.
//   h_V    = LN(node_rbf(96) @ node_W^T + node_b)        [N,128]
//   h_E_*  = LN(edge_feats(268) @ edge_W^T + edge_b)     [E,128] x2
// Edge GEMM on HMMA (mma.sync m16n8k16 bf16, 3-pass hi/lo = fp32-grade).
// All 16 warps issue MMA; featgen software-pipelined with idx prefetch.
// ===========================================================================

#define QMAX 131072
__device__ float g_Q[QMAX * 9];   // per-node frame: b1(3), n0(3), b2(3)

__device__ __constant__ int c_NA[6]  = {1, 1, 1, 0, 0, 3};
__device__ __constant__ int c_NB[6]  = {0, 2, 3, 2, 3, 2};
__device__ __constant__ int c_EA[16] = {1,1,2,1,0,1,3,2,2,0,2,3,0,0,3,3};
__device__ __constant__ int c_EB[16] = {1,2,1,0,1,3,1,2,0,2,3,2,0,3,0,3};
__device__ __constant__ int c_AMAP[4] = {1, 0, 2, 3};

// ------------------------------ helpers ------------------------------------
__device__ __forceinline__ uint32_t smem_to_u32(const void* p) {
    uint32_t a;
    asm("{ .reg .u64 t; cvta.to.shared.u64 t, %1; cvt.u32.u64 %0, t; }"
        : "=r"(a) : "l"(p));
    return a;
}
__device__ __forceinline__ void ldsm4(uint32_t* r, uint32_t addr) {
    asm volatile("ldmatrix.sync.aligned.m8n8.x4.shared.b16 {%0,%1,%2,%3}, [%4];"
        : "=r"(r[0]), "=r"(r[1]), "=r"(r[2]), "=r"(r[3]) : "r"(addr));
}
__device__ __forceinline__ void mma_bf16(float* d, const uint32_t* a,
                                         uint32_t b0, uint32_t b1) {
    asm volatile("mma.sync.aligned.m16n8k16.row.col.f32.bf16.bf16.f32 "
        "{%0,%1,%2,%3}, {%4,%5,%6,%7}, {%8,%9}, {%0,%1,%2,%3};"
        : "+f"(d[0]), "+f"(d[1]), "+f"(d[2]), "+f"(d[3])
        : "r"(a[0]), "r"(a[1]), "r"(a[2]), "r"(a[3]), "r"(b0), "r"(b1));
}
__device__ __forceinline__ uint32_t pk2(float a, float b) {
    uint32_t lo = __bfloat16_as_ushort(__float2bfloat16(a));
    uint32_t hi = __bfloat16_as_ushort(__float2bfloat16(b));
    return (hi << 16) | lo;
}
__device__ __forceinline__ float bfres(float x) {   // x - bf16(x)
    return x - __bfloat162float(__float2bfloat16(x));
}

// --------------------------- frame precompute ------------------------------
__global__ void q_kernel(const float* __restrict__ X, int N) {
    int i = blockIdx.x * blockDim.x + threadIdx.x;
    if (i >= N) return;
    float* q = &g_Q[i * 9];
    if (i == N - 1) {
        #pragma unroll
        for (int j = 0; j < 9; j++) q[j] = 0.f;
        return;
    }
    const float* x = X + (size_t)i * 12;
    float ax = x[3] - x[0], ay = x[4] - x[1], az = x[5] - x[2];
    float n = sqrtf(ax*ax + ay*ay + az*az); if (n == 0.f) n = 1.f;
    float r = 1.f / n;
    float u0x = ax*r, u0y = ay*r, u0z = az*r;
    float bx = x[6] - x[3], by = x[7] - x[4], bz = x[8] - x[5];
    n = sqrtf(bx*bx + by*by + bz*bz); if (n == 0.f) n = 1.f;
    r = 1.f / n;
    float u1x = bx*r, u1y = by*r, u1z = bz*r;
    float cx = u0y*u1z - u0z*u1y, cy = u0z*u1x - u0x*u1z, cz = u0x*u1y - u0y*u1x;
    n = sqrtf(cx*cx + cy*cy + cz*cz); if (n == 0.f) n = 1.f;
    r = 1.f / n;
    float n0x = cx*r, n0y = cy*r, n0z = cz*r;
    float dx = u0x-u1x, dy = u0y-u1y, dz = u0z-u1z;
    n = sqrtf(dx*dx + dy*dy + dz*dz); if (n == 0.f) n = 1.f;
    r = 1.f / n;
    float b1x = dx*r, b1y = dy*r, b1z = dz*r;
    q[0]=b1x; q[1]=b1y; q[2]=b1z;
    q[3]=n0x; q[4]=n0y; q[5]=n0z;
    q[6]=b1y*n0z-b1z*n0y; q[7]=b1z*n0x-b1x*n0z; q[8]=b1x*n0y-b1y*n0x;
}

// ------------------------------ node kernel --------------------------------
#define NODE_SMEM_FLOATS (96 * 128 + 96 + 12 + 8)
__global__ __launch_bounds__(128) void node_kernel(
    const float* __restrict__ X, const float* __restrict__ W,
    const float* __restrict__ b, const float* __restrict__ gain,
    const float* __restrict__ bias, float* __restrict__ out, int N)
{
    extern __shared__ float sm[];
    float* Wsh  = sm;
    float* feat = Wsh + 96 * 128;
    float* xsh  = feat + 96;
    float* red  = xsh + 12;
    int t = threadIdx.x;
    for (int i = t; i < 96 * 128; i += 128) {
        int o = i / 96, f = i - o * 96;
        Wsh[f * 128 + o] = W[i];
    }
    float nb = b[t], ng = gain[t], nbi = bias[t];
    __syncthreads();
    for (int i = blockIdx.x; i < N; i += gridDim.x) {
        if (t < 12) xsh[t] = X[(size_t)i * 12 + t];
        __syncthreads();
        if (t < 96) {
            int p = t >> 4, k = t & 15;
            int a = c_NA[p], bb = c_NB[p];
            float dx = xsh[a*3+0]-xsh[bb*3+0], dy = xsh[a*3+1]-xsh[bb*3+1], dz = xsh[a*3+2]-xsh[bb*3+2];
            float D = sqrtf(dx*dx + dy*dy + dz*dz + 1e-6f);
            float z = (D - (float)k * (20.f/15.f)) * 0.8f;
            feat[t] = __expf(-z * z);
        }
        __syncthreads();
        float acc = nb;
        #pragma unroll 8
        for (int f = 0; f < 96; f++) acc += feat[f] * Wsh[f * 128 + t];
        float s = acc, sq = acc * acc;
        #pragma unroll
        for (int off = 16; off; off >>= 1) {
            s  += __shfl_down_sync(0xffffffffu, s, off);
            sq += __shfl_down_sync(0xffffffffu, sq, off);
        }
        if ((t & 31) == 0) { red[(t>>5)*2] = s; red[(t>>5)*2+1] = sq; }
        __syncthreads();
        float S  = red[0]+red[2]+red[4]+red[6];
        float Sq = red[1]+red[3]+red[5]+red[7];
        float mu = S * (1.f/128.f);
        float sig = sqrtf((Sq - S*mu) * (1.f/127.f) + 1e-6f);
        out[(size_t)i * 128 + t] = ng * (acc - mu) / (sig + 1e-6f) + nbi;
        __syncthreads();
    }
}

// ------------------------- edge HMMA kernel (v3) ---------------------------
// 512 thr, 16 warps, ALL do MMA. Tile=32 edges. Warp = 16 edges x 16 outs.
// Per iter: prefetch idx(next) -> MMA(cur) -> red partials -> featgen(next)
// -> syncthreads -> LN+store(cur).  A tiles double-buffered; red double-buf.
#define ROWB      560                        // 35*16B; 35%8=3 -> ldsm conflict-free
#define OFF_PAR   0                          // eb/gain/bias: 1536 B
#define OFF_RED   1536                       // 2 stages x (32 e x 8 og x float2)
#define RED_STAGE 2048
#define OFF_BHI   (OFF_RED + 2*RED_STAGE)    // 5632
#define OFF_BLO   (OFF_BHI + 128*ROWB)       // 77312
#define OFF_A     (OFF_BLO + 128*ROWB)       // 148992
#define A_HALF    (32*ROWB)                  // 17920
#define A_STAGE   (2*A_HALF)                 // 35840
#define EDGE_SMEM (OFF_A + 2*A_STAGE)        // 220672

// featgen for one (edge, pair) unit + optional orientation (p==8 thread).
__device__ __forceinline__ void featgen_unit(
    char* smem, char* aHb, char* aLb, const float* __restrict__ X,
    int el, int p, int si, int di)
{
    const float* xs_ = X + (size_t)si * 12;
    const float* xd_ = X + (size_t)di * 12;
    {
        const float* xa = xs_ + c_EA[p] * 3;
        const float* xb = xd_ + c_EB[p] * 3;
        float dx = xa[0]-xb[0], dy = xa[1]-xb[1], dz = xa[2]-xb[2];
        float D = sqrtf(dx*dx + dy*dy + dz*dz + 1e-6f);
        float f[16];
        #pragma unroll
        for (int k = 0; k < 16; k++) {
            float z = (D - (float)k * (20.f/15.f)) * 0.8f;
            f[k] = __expf(-z * z);
        }
        uint32_t hw[8], lw[8];
        #pragma unroll
        for (int k = 0; k < 8; k++) {
            hw[k] = pk2(f[2*k], f[2*k+1]);
            lw[k] = pk2(bfres(f[2*k]), bfres(f[2*k+1]));
        }
        char* ah = aHb + el*ROWB + p*32;
        char* al = aLb + el*ROWB + p*32;
        *(uint4*)(ah)      = make_uint4(hw[0],hw[1],hw[2],hw[3]);
        *(uint4*)(ah + 16) = make_uint4(hw[4],hw[5],hw[6],hw[7]);
        *(uint4*)(al)      = make_uint4(lw[0],lw[1],lw[2],lw[3]);
        *(uint4*)(al + 16) = make_uint4(lw[4],lw[5],lw[6],lw[7]);
    }
    if (p == 8) {    // orientation features, cols 256..271
        float ox = xs_[0], oy = xs_[1], oz = xs_[2];
        const float* q = g_Q + (size_t)si * 9;
        float q0=q[0],q1=q[1],q2=q[2],q3=q[3],q4=q[4],
              q5=q[5],q6=q[6],q7=q[7],q8=q[8];
        float fv[12];
        #pragma unroll
        for (int a = 0; a < 4; a++) {
            int da = c_AMAP[a];
            float px = xd_[da*3+0]-ox, py = xd_[da*3+1]-oy, pz = xd_[da*3+2]-oz;
            float vx = q0*px + q3*py + q6*pz;
            float vy = q1*px + q4*py + q7*pz;
            float vz = q2*px + q5*py + q8*pz;
            float n = sqrtf(vx*vx + vy*vy + vz*vz);
            if (n == 0.f) n = 1.f;
            float r = 1.f / n;
            fv[a*3+0] = vx*r; fv[a*3+1] = vy*r; fv[a*3+2] = vz*r;
        }
        uint32_t hw[8], lw[8];
        #pragma unroll
        for (int k = 0; k < 6; k++) {
            hw[k] = pk2(fv[2*k], fv[2*k+1]);
            lw[k] = pk2(bfres(fv[2*k]), bfres(fv[2*k+1]));
        }
        hw[6] = hw[7] = lw[6] = lw[7] = 0u;
        char* ah = aHb + el*ROWB + 512;
        char* al = aLb + el*ROWB + 512;
        *(uint4*)(ah)      = make_uint4(hw[0],hw[1],hw[2],hw[3]);
        *(uint4*)(ah + 16) = make_uint4(hw[4],hw[5],hw[6],hw[7]);
        *(uint4*)(al)      = make_uint4(lw[0],lw[1],lw[2],lw[3]);
        *(uint4*)(al + 16) = make_uint4(lw[4],lw[5],lw[6],lw[7]);
    }
}

__global__ __launch_bounds__(512, 1)
void edge_hmma_kernel(const float* __restrict__ X,
                      const int* __restrict__ idx1, const int* __restrict__ idx2,
                      int E, const float* __restrict__ W,
                      const float* __restrict__ eb, const float* __restrict__ egain,
                      const float* __restrict__ ebias,
                      float* __restrict__ out1, float* __restrict__ out2)
{
    extern __shared__ char smem[];
    uint32_t sb = smem_to_u32(smem);
    int t = threadIdx.x;

    // ---- one-time staging: params + W -> bf16 hi/lo ----
    if (t < 128) {
        ((float*)(smem + OFF_PAR))[t]       = eb[t];
        ((float*)(smem + OFF_PAR))[128 + t] = egain[t];
        ((float*)(smem + OFF_PAR))[256 + t] = ebias[t];
    }
    for (int i = t; i < 128 * 268; i += 512) {
        int r = i / 268, k = i - r * 268;
        float w = W[i];
        float hi = __bfloat162float(__float2bfloat16(w));
        *(uint16_t*)(smem + OFF_BHI + r*ROWB + k*2) =
            __bfloat16_as_ushort(__float2bfloat16(w));
        *(uint16_t*)(smem + OFF_BLO + r*ROWB + k*2) =
            __bfloat16_as_ushort(__float2bfloat16(w - hi));
    }
    for (int i = t; i < 128 * 4; i += 512) {       // zero W cols 268..271
        int r = i >> 2, c = 268 + (i & 3);
        *(uint16_t*)(smem + OFF_BHI + r*ROWB + c*2) = 0;
        *(uint16_t*)(smem + OFF_BLO + r*ROWB + c*2) = 0;
    }
    __syncthreads();

    const int ntiles  = (E + 31) >> 5;
    const int ntiles2 = ntiles * 2;
    const int grid    = gridDim.x;

    int wid = t >> 5, lane = t & 31;
    int egrp = wid & 1, og = wid >> 1;
    int t4 = lane & 3, g = lane >> 2;
    uint32_t aOff = (uint32_t)(egrp*16 + (lane & 15)) * ROWB
                  + ((lane & 16) ? 16u : 0u);
    uint32_t bRow = (uint32_t)(og*16 + (lane & 7) + ((lane & 16) >> 1));
    uint32_t bOff = bRow * ROWB + ((lane & 8) ? 16u : 0u);
    uint32_t bHiA = sb + OFF_BHI + bOff;
    uint32_t bLoA = sb + OFF_BLO + bOff;

    int el = t >> 4, p = t & 15;    // featgen unit mapping

    int tile = blockIdx.x;
    int it = 0;

    // ---- prologue: featgen tile0 into stage 0 ----
    if (tile < ntiles2) {
        bool ex = tile >= ntiles;
        const int* ix = ex ? idx2 : idx1;
        int ebase = (ex ? tile - ntiles : tile) * 32;
        int ge = ebase + el;
        if (ge < E) {
            int si = ix[ge], di = ix[E + ge];
            featgen_unit(smem, smem + OFF_A, smem + OFF_A + A_HALF, X, el, p, si, di);
        }
        __syncthreads();
    }

    for (; tile < ntiles2; tile += grid, it++) {
        int s = it & 1;

        // ---- prefetch idx for next tile (issue LDG early) ----
        int ntile = tile + grid;
        int nsi = 0, ndi = 0;
        bool nvalid = false;
        if (ntile < ntiles2) {
            bool nex = ntile >= ntiles;
            const int* nix = nex ? idx2 : idx1;
            int nebase = (nex ? ntile - ntiles : ntile) * 32;
            int nge = nebase + el;
            if (nge < E) { nsi = nix[nge]; ndi = nix[E + nge]; nvalid = true; }
        }

        // ---- MMA tile from stage s ----
        uint32_t aHi = sb + OFF_A + s*A_STAGE + aOff;
        uint32_t aLo = aHi + A_HALF;
        float acc[2][4];
        acc[0][0]=acc[0][1]=acc[0][2]=acc[0][3]=0.f;
        acc[1][0]=acc[1][1]=acc[1][2]=acc[1][3]=0.f;

        #pragma unroll 1
        for (int ks = 0; ks < 17; ks++) {
            uint32_t ko = (uint32_t)ks * 32;
            uint32_t aH[4], aL[4], bH[4], bL[4];
            ldsm4(aH, aHi + ko);
            ldsm4(bH, bHiA + ko);
            ldsm4(aL, aLo + ko);
            ldsm4(bL, bLoA + ko);
            mma_bf16(acc[0], aH, bH[0], bH[1]);
            mma_bf16(acc[1], aH, bH[2], bH[3]);
            mma_bf16(acc[0], aL, bH[0], bH[1]);
            mma_bf16(acc[1], aL, bH[2], bH[3]);
            mma_bf16(acc[0], aH, bL[0], bL[1]);
            mma_bf16(acc[1], aH, bL[2], bL[3]);
        }

        // ---- bias + LN partials into red[s] ----
        bool ex = tile >= ntiles;
        int ebase = (ex ? tile - ntiles : tile) * 32;
        float* outp = ex ? out2 : out1;

        float S0=0, Q0=0, S1=0, Q1=0;
        #pragma unroll
        for (int n = 0; n < 2; n++) {
            int col = og*16 + n*8 + t4*2;
            float2 b2 = *(const float2*)(smem + OFF_PAR + col*4);
            acc[n][0] += b2.x; acc[n][1] += b2.y;
            acc[n][2] += b2.x; acc[n][3] += b2.y;
            S0 += acc[n][0] + acc[n][1];
            Q0 += acc[n][0]*acc[n][0] + acc[n][1]*acc[n][1];
            S1 += acc[n][2] + acc[n][3];
            Q1 += acc[n][2]*acc[n][2] + acc[n][3]*acc[n][3];
        }
        #pragma unroll
        for (int off = 1; off <= 2; off <<= 1) {
            S0 += __shfl_xor_sync(0xffffffffu, S0, off);
            Q0 += __shfl_xor_sync(0xffffffffu, Q0, off);
            S1 += __shfl_xor_sync(0xffffffffu, S1, off);
            Q1 += __shfl_xor_sync(0xffffffffu, Q1, off);
        }
        float2* red = (float2*)(smem + OFF_RED + s*RED_STAGE);
        int e0 = egrp*16 + g, e1 = e0 + 8;
        if (t4 == 0) {
            red[e0*8 + og] = make_float2(S0, Q0);
            red[e1*8 + og] = make_float2(S1, Q1);
        }

        // ---- featgen next tile into stage s^1 ----
        if (nvalid) {
            char* aHb = smem + OFF_A + (s^1)*A_STAGE;
            featgen_unit(smem, aHb, aHb + A_HALF, X, el, p, nsi, ndi);
        }
        __syncthreads();

        // ---- LN finalize + store ----
        float St0=0, Qt0=0, St1=0, Qt1=0;
        #pragma unroll
        for (int q = 0; q < 8; q++) {
            float2 r0 = red[e0*8 + q]; St0 += r0.x; Qt0 += r0.y;
            float2 r1 = red[e1*8 + q]; St1 += r1.x; Qt1 += r1.y;
        }
        float mu0 = St0 * (1.f/128.f);
        float rs0 = 1.f / (sqrtf((Qt0 - St0*mu0) * (1.f/127.f) + 1e-6f) + 1e-6f);
        float mu1 = St1 * (1.f/128.f);
        float rs1 = 1.f / (sqrtf((Qt1 - St1*mu1) * (1.f/127.f) + 1e-6f) + 1e-6f);

        int ge0 = ebase + e0, ge1 = ebase + e1;
        float* op0 = outp + (size_t)ge0 * 128;
        float* op1 = outp + (size_t)ge1 * 128;
        #pragma unroll
        for (int n = 0; n < 2; n++) {
            int col = og*16 + n*8 + t4*2;
            float2 gn2 = *(const float2*)(smem + OFF_PAR + 512 + col*4);
            float2 bs2 = *(const float2*)(smem + OFF_PAR + 1024 + col*4);
            if (ge0 < E) {
                float2 o;
                o.x = gn2.x * (acc[n][0] - mu0) * rs0 + bs2.x;
                o.y = gn2.y * (acc[n][1] - mu0) * rs0 + bs2.y;
                __stcs((float2*)(op0 + col), o);
            }
            if (ge1 < E) {
                float2 o;
                o.x = gn2.x * (acc[n][2] - mu1) * rs1 + bs2.x;
                o.y = gn2.y * (acc[n][3] - mu1) * rs1 + bs2.y;
                __stcs((float2*)(op1 + col), o);
            }
        }
    }
}

// ------------------------------- launcher ----------------------------------
extern "C" void kernel_launch(void* const* d_in, const int* in_sizes, int n_in,
                              void* d_out, int out_size)
{
    const float* X   = (const float*)d_in[0];
    const int*   Ein = (const int*)d_in[1];
    const int*   Eex = (const int*)d_in[2];
    const float* nW  = (const float*)d_in[3];
    const float* nb  = (const float*)d_in[4];
    const float* eW  = (const float*)d_in[5];
    const float* eb  = (const float*)d_in[6];
    const float* gn  = (const float*)d_in[7];
    const float* bn  = (const float*)d_in[8];
    const float* ge  = (const float*)d_in[9];
    const float* be  = (const float*)d_in[10];

    int N = in_sizes[0] / 12;
    int E = in_sizes[1] / 2;
    float* out = (float*)d_out;

    cudaFuncSetAttribute(node_kernel, cudaFuncAttributeMaxDynamicSharedMemorySize,
                         NODE_SMEM_FLOATS * 4);
    cudaFuncSetAttribute(edge_hmma_kernel, cudaFuncAttributeMaxDynamicSharedMemorySize,
                         EDGE_SMEM);

    int sms = 148;
    cudaDeviceGetAttribute(&sms, cudaDevAttrMultiProcessorCount, 0);

    q_kernel<<<(N + 127) / 128, 128>>>(X, N);
    node_kernel<<<512, 128, NODE_SMEM_FLOATS * 4>>>(X, nW, nb, gn, bn, out, N);

    float* out_in = out + (size_t)N * 128;
    float* out_ex = out_in + (size_t)E * 128;
    edge_hmma_kernel<<<sms, 512, EDGE_SMEM>>>(X, Ein, Eex, E, eW, eb, ge, be,
                                              out_in, out_ex);
}

// round 10
// speedup vs baseline: 1.8101x; 1.8101x over previous
#include <cuda_runtime.h>
#include <cuda_fp16.h>
#include <cstdint>

// ===========================================================================
// Protein graph featurization.
//   h_V    = LN(node_rbf(96) @ node_W^T + node_b)        [N,128]
//   h_E_*  = LN(edge_feats(268) @ edge_W^T + edge_b)     [E,128] x2
// Edge GEMM on HMMA mma.sync m16n8k16 fp16, 2-pass A-hi/lo (B rounded once:
// rel err ~2e-4 < 1e-3). Producer/consumer warp specialization (round-6
// skeleton), 64-edge tiles, A double-buffered.
// ===========================================================================

#define QMAX 131072
__device__ float g_Q[QMAX * 9];   // per-node frame: b1(3), n0(3), b2(3)

__device__ __constant__ int c_NA[6]  = {1, 1, 1, 0, 0, 3};
__device__ __constant__ int c_NB[6]  = {0, 2, 3, 2, 3, 2};
__device__ __constant__ int c_EA[16] = {1,1,2,1,0,1,3,2,2,0,2,3,0,0,3,3};
__device__ __constant__ int c_EB[16] = {1,2,1,0,1,3,1,2,0,2,3,2,0,3,0,3};
__device__ __constant__ int c_AMAP[4] = {1, 0, 2, 3};

// ------------------------------ helpers ------------------------------------
__device__ __forceinline__ uint32_t smem_to_u32(const void* p) {
    uint32_t a;
    asm("{ .reg .u64 t; cvta.to.shared.u64 t, %1; cvt.u32.u64 %0, t; }"
        : "=r"(a) : "l"(p));
    return a;
}
__device__ __forceinline__ void ldsm4(uint32_t* r, uint32_t addr) {
    asm volatile("ldmatrix.sync.aligned.m8n8.x4.shared.b16 {%0,%1,%2,%3}, [%4];"
        : "=r"(r[0]), "=r"(r[1]), "=r"(r[2]), "=r"(r[3]) : "r"(addr));
}
__device__ __forceinline__ void mma_f16(float* d, const uint32_t* a,
                                        uint32_t b0, uint32_t b1) {
    asm volatile("mma.sync.aligned.m16n8k16.row.col.f32.f16.f16.f32 "
        "{%0,%1,%2,%3}, {%4,%5,%6,%7}, {%8,%9}, {%0,%1,%2,%3};"
        : "+f"(d[0]), "+f"(d[1]), "+f"(d[2]), "+f"(d[3])
        : "r"(a[0]), "r"(a[1]), "r"(a[2]), "r"(a[3]), "r"(b0), "r"(b1));
}
#define BAR_SYNC(id, cnt) \
    asm volatile("bar.sync %0, %1;" :: "r"(id), "r"(cnt) : "memory")
#define BAR_ARRIVE(id, cnt) \
    asm volatile("bar.arrive %0, %1;" :: "r"(id), "r"(cnt) : "memory")

__device__ __forceinline__ uint32_t pk2h(float a, float b) {
    __half2 h = __floats2half2_rn(a, b);
    return *(uint32_t*)&h;
}
__device__ __forceinline__ float hres(float x) {   // x - fp16(x)
    return x - __half2float(__float2half_rn(x));
}

// --------------------------- frame precompute ------------------------------
__global__ void q_kernel(const float* __restrict__ X, int N) {
    int i = blockIdx.x * blockDim.x + threadIdx.x;
    if (i >= N) return;
    float* q = &g_Q[i * 9];
    if (i == N - 1) {
        #pragma unroll
        for (int j = 0; j < 9; j++) q[j] = 0.f;
        return;
    }
    const float* x = X + (size_t)i * 12;
    float ax = x[3] - x[0], ay = x[4] - x[1], az = x[5] - x[2];
    float n = sqrtf(ax*ax + ay*ay + az*az); if (n == 0.f) n = 1.f;
    float r = 1.f / n;
    float u0x = ax*r, u0y = ay*r, u0z = az*r;
    float bx = x[6] - x[3], by = x[7] - x[4], bz = x[8] - x[5];
    n = sqrtf(bx*bx + by*by + bz*bz); if (n == 0.f) n = 1.f;
    r = 1.f / n;
    float u1x = bx*r, u1y = by*r, u1z = bz*r;
    float cx = u0y*u1z - u0z*u1y, cy = u0z*u1x - u0x*u1z, cz = u0x*u1y - u0y*u1x;
    n = sqrtf(cx*cx + cy*cy + cz*cz); if (n == 0.f) n = 1.f;
    r = 1.f / n;
    float n0x = cx*r, n0y = cy*r, n0z = cz*r;
    float dx = u0x-u1x, dy = u0y-u1y, dz = u0z-u1z;
    n = sqrtf(dx*dx + dy*dy + dz*dz); if (n == 0.f) n = 1.f;
    r = 1.f / n;
    float b1x = dx*r, b1y = dy*r, b1z = dz*r;
    q[0]=b1x; q[1]=b1y; q[2]=b1z;
    q[3]=n0x; q[4]=n0y; q[5]=n0z;
    q[6]=b1y*n0z-b1z*n0y; q[7]=b1z*n0x-b1x*n0z; q[8]=b1x*n0y-b1y*n0x;
}

// ------------------------------ node kernel --------------------------------
#define NODE_SMEM_FLOATS (96 * 128 + 96 + 12 + 8)
__global__ __launch_bounds__(128) void node_kernel(
    const float* __restrict__ X, const float* __restrict__ W,
    const float* __restrict__ b, const float* __restrict__ gain,
    const float* __restrict__ bias, float* __restrict__ out, int N)
{
    extern __shared__ float sm[];
    float* Wsh  = sm;
    float* feat = Wsh + 96 * 128;
    float* xsh  = feat + 96;
    float* red  = xsh + 12;
    int t = threadIdx.x;
    for (int i = t; i < 96 * 128; i += 128) {
        int o = i / 96, f = i - o * 96;
        Wsh[f * 128 + o] = W[i];
    }
    float nb = b[t], ng = gain[t], nbi = bias[t];
    __syncthreads();
    for (int i = blockIdx.x; i < N; i += gridDim.x) {
        if (t < 12) xsh[t] = X[(size_t)i * 12 + t];
        __syncthreads();
        if (t < 96) {
            int p = t >> 4, k = t & 15;
            int a = c_NA[p], bb = c_NB[p];
            float dx = xsh[a*3+0]-xsh[bb*3+0], dy = xsh[a*3+1]-xsh[bb*3+1], dz = xsh[a*3+2]-xsh[bb*3+2];
            float D = sqrtf(dx*dx + dy*dy + dz*dz + 1e-6f);
            float z = (D - (float)k * (20.f/15.f)) * 0.8f;
            feat[t] = __expf(-z * z);
        }
        __syncthreads();
        float acc = nb;
        #pragma unroll 8
        for (int f = 0; f < 96; f++) acc += feat[f] * Wsh[f * 128 + t];
        float s = acc, sq = acc * acc;
        #pragma unroll
        for (int off = 16; off; off >>= 1) {
            s  += __shfl_down_sync(0xffffffffu, s, off);
            sq += __shfl_down_sync(0xffffffffu, sq, off);
        }
        if ((t & 31) == 0) { red[(t>>5)*2] = s; red[(t>>5)*2+1] = sq; }
        __syncthreads();
        float S  = red[0]+red[2]+red[4]+red[6];
        float Sq = red[1]+red[3]+red[5]+red[7];
        float mu = S * (1.f/128.f);
        float sig = sqrtf((Sq - S*mu) * (1.f/127.f) + 1e-6f);
        out[(size_t)i * 128 + t] = ng * (acc - mu) / (sig + 1e-6f) + nbi;
        __syncthreads();
    }
}

// ---------------------- edge HMMA kernel (fp16 2-pass) ---------------------
// 512 thr: warps 0-7 consumers (warp = 16 edges x 64 cols), warps 8-15
// producers. Tile = 64 edges, A (hi+lo fp16) double-buffered, B fp16 hi only.
// Row stride 560B = 35*16B (35%8=3 -> ldmatrix conflict-free).
#define ROWB      560
#define OFF_PAR   0                          // eb/gain/bias: 1536 B
#define OFF_RED   1536                       // 2 x (64 e x 2 halves x float2)
#define RED_STAGE 1024
#define OFF_BHI   (OFF_RED + 2*RED_STAGE)    // 3584
#define OFF_A     (OFF_BHI + 128*ROWB)       // 75264
#define A_HALF    (64*ROWB)                  // 35840
#define A_STAGE   (2*A_HALF)                 // 71680
#define EDGE_SMEM (OFF_A + 2*A_STAGE)        // 218624
// named barriers: 1,2 = full[s]; 3,4 = empty[s]; 5 = consumers; 6 = producers

__global__ __launch_bounds__(512, 1)
void edge_hmma_kernel(const float* __restrict__ X,
                      const int* __restrict__ idx1, const int* __restrict__ idx2,
                      int E, const float* __restrict__ W,
                      const float* __restrict__ eb, const float* __restrict__ egain,
                      const float* __restrict__ ebias,
                      float* __restrict__ out1, float* __restrict__ out2)
{
    extern __shared__ char smem[];
    uint32_t sb = smem_to_u32(smem);
    int t = threadIdx.x;

    // ---- one-time staging: params + W -> fp16 in SMEM ----
    if (t < 128) {
        ((float*)(smem + OFF_PAR))[t]       = eb[t];
        ((float*)(smem + OFF_PAR))[128 + t] = egain[t];
        ((float*)(smem + OFF_PAR))[256 + t] = ebias[t];
    }
    for (int i = t; i < 128 * 268; i += 512) {
        int r = i / 268, k = i - r * 268;
        *(__half*)(smem + OFF_BHI + r*ROWB + k*2) = __float2half_rn(W[i]);
    }
    for (int i = t; i < 128 * 4; i += 512) {       // zero W cols 268..271
        int r = i >> 2, c = 268 + (i & 3);
        *(uint16_t*)(smem + OFF_BHI + r*ROWB + c*2) = 0;
    }
    __syncthreads();

    const int ntiles  = (E + 63) >> 6;
    const int ntiles2 = ntiles * 2;
    const int grid    = gridDim.x;

    if (t < 256) {
        // =========================== CONSUMER ===========================
        // warp = egrp(4) x 16 edges, nhalf(2) x 64 cols  (round-3 mapping)
        int wid = t >> 5, lane = t & 31;
        int egrp = wid & 3, nhalf = wid >> 2;
        int t4 = lane & 3, g = lane >> 2;
        uint32_t aOff = (uint32_t)(egrp*16 + (lane & 15)) * ROWB
                      + ((lane & 16) ? 16u : 0u);
        uint32_t bRow = (uint32_t)(nhalf*64 + ((lane & 7) | ((lane & 16) >> 1)));
        uint32_t bOff = bRow * ROWB + ((lane & 8) ? 16u : 0u);
        uint32_t bHiA = sb + OFF_BHI + bOff;

        int it = 0;
        for (int tile = blockIdx.x; tile < ntiles2; tile += grid, it++) {
            int s = it & 1;
            bool ex = tile >= ntiles;
            int ebase = (ex ? tile - ntiles : tile) * 64;
            float* outp = ex ? out2 : out1;
            uint32_t aHi = sb + OFF_A + s*A_STAGE + aOff;
            uint32_t aLo = aHi + A_HALF;

            BAR_SYNC(1 + s, 512);                     // wait full

            float acc[8][4];
            #pragma unroll
            for (int n = 0; n < 8; n++)
                acc[n][0] = acc[n][1] = acc[n][2] = acc[n][3] = 0.f;

            #pragma unroll 1
            for (int ks = 0; ks < 17; ks++) {
                uint32_t ko = (uint32_t)ks * 32;
                uint32_t aH[4], aL[4], bF[4][4];
                ldsm4(aH, aHi + ko);
                ldsm4(aL, aLo + ko);
                #pragma unroll
                for (int np = 0; np < 4; np++)
                    ldsm4(bF[np], bHiA + np*(16*ROWB) + ko);
                #pragma unroll
                for (int n = 0; n < 8; n++)
                    mma_f16(acc[n], aH, bF[n>>1][(n&1)*2], bF[n>>1][(n&1)*2+1]);
                #pragma unroll
                for (int n = 0; n < 8; n++)
                    mma_f16(acc[n], aL, bF[n>>1][(n&1)*2], bF[n>>1][(n&1)*2+1]);
            }
            BAR_ARRIVE(3 + s, 512);                   // signal empty

            // ---- epilogue: bias + LN (cross-half) + store ----
            int e0 = egrp*16 + g, e1 = e0 + 8;
            float S0=0, Q0=0, S1=0, Q1=0;
            #pragma unroll
            for (int n = 0; n < 8; n++) {
                int col = nhalf*64 + n*8 + t4*2;
                float2 b2 = *(const float2*)(smem + OFF_PAR + col*4);
                acc[n][0] += b2.x; acc[n][1] += b2.y;
                acc[n][2] += b2.x; acc[n][3] += b2.y;
                S0 += acc[n][0] + acc[n][1];
                Q0 += acc[n][0]*acc[n][0] + acc[n][1]*acc[n][1];
                S1 += acc[n][2] + acc[n][3];
                Q1 += acc[n][2]*acc[n][2] + acc[n][3]*acc[n][3];
            }
            #pragma unroll
            for (int off = 1; off <= 2; off <<= 1) {
                S0 += __shfl_xor_sync(0xffffffffu, S0, off);
                Q0 += __shfl_xor_sync(0xffffffffu, Q0, off);
                S1 += __shfl_xor_sync(0xffffffffu, S1, off);
                Q1 += __shfl_xor_sync(0xffffffffu, Q1, off);
            }
            float2* red = (float2*)(smem + OFF_RED + s*RED_STAGE);
            if (t4 == 0) {
                red[e0*2 + nhalf] = make_float2(S0, Q0);
                red[e1*2 + nhalf] = make_float2(S1, Q1);
            }
            BAR_SYNC(5, 256);
            float2 ra = red[e0*2], rb = red[e0*2+1];
            float St0 = ra.x + rb.x, Qt0 = ra.y + rb.y;
            float2 rc = red[e1*2], rd = red[e1*2+1];
            float St1 = rc.x + rd.x, Qt1 = rc.y + rd.y;
            float mu0 = St0 * (1.f/128.f);
            float rs0 = 1.f / (sqrtf((Qt0 - St0*mu0) * (1.f/127.f) + 1e-6f) + 1e-6f);
            float mu1 = St1 * (1.f/128.f);
            float rs1 = 1.f / (sqrtf((Qt1 - St1*mu1) * (1.f/127.f) + 1e-6f) + 1e-6f);

            int ge0 = ebase + e0, ge1 = ebase + e1;
            float* op0 = outp + (size_t)ge0 * 128;
            float* op1 = outp + (size_t)ge1 * 128;
            #pragma unroll
            for (int n = 0; n < 8; n++) {
                int col = nhalf*64 + n*8 + t4*2;
                float2 gn2 = *(const float2*)(smem + OFF_PAR + 512 + col*4);
                float2 bs2 = *(const float2*)(smem + OFF_PAR + 1024 + col*4);
                if (ge0 < E) {
                    float2 o;
                    o.x = gn2.x * (acc[n][0] - mu0) * rs0 + bs2.x;
                    o.y = gn2.y * (acc[n][1] - mu0) * rs0 + bs2.y;
                    __stcs((float2*)(op0 + col), o);
                }
                if (ge1 < E) {
                    float2 o;
                    o.x = gn2.x * (acc[n][2] - mu1) * rs1 + bs2.x;
                    o.y = gn2.y * (acc[n][3] - mu1) * rs1 + bs2.y;
                    __stcs((float2*)(op1 + col), o);
                }
            }
        }
    } else {
        // =========================== PRODUCER ===========================
        int t2 = t - 256;
        int el = t2 & 63;        // edge within tile
        int pu = t2 >> 6;        // pair quarter: pairs pu*4 .. pu*4+3

        int it = 0;
        for (int tile = blockIdx.x; tile < ntiles2; tile += grid, it++) {
            int s = it & 1;
            bool ex = tile >= ntiles;
            int ebase = (ex ? tile - ntiles : tile) * 64;
            const int* ix = ex ? idx2 : idx1;
            char* aHb = smem + OFF_A + s*A_STAGE;
            char* aLb = aHb + A_HALF;

            if (it >= 2) BAR_SYNC(3 + s, 512);         // wait empty

            int ge = ebase + el;
            if (ge < E) {
                int sidx = ix[ge], didx = ix[E + ge];
                const float* xs_ = X + (size_t)sidx * 12;
                const float* xd_ = X + (size_t)didx * 12;

                #pragma unroll
                for (int j = 0; j < 4; j++) {
                    int p = pu * 4 + j;
                    const float* xa = xs_ + c_EA[p] * 3;
                    const float* xb = xd_ + c_EB[p] * 3;
                    float dx = xa[0]-xb[0], dy = xa[1]-xb[1], dz = xa[2]-xb[2];
                    float D = sqrtf(dx*dx + dy*dy + dz*dz + 1e-6f);
                    float f[16];
                    #pragma unroll
                    for (int k = 0; k < 16; k++) {
                        float z = (D - (float)k * (20.f/15.f)) * 0.8f;
                        f[k] = __expf(-z * z);
                    }
                    uint32_t hw[8], lw[8];
                    #pragma unroll
                    for (int k = 0; k < 8; k++) {
                        hw[k] = pk2h(f[2*k], f[2*k+1]);
                        lw[k] = pk2h(hres(f[2*k]), hres(f[2*k+1]));
                    }
                    char* ah = aHb + el*ROWB + p*32;
                    char* al = aLb + el*ROWB + p*32;
                    *(uint4*)(ah)      = make_uint4(hw[0],hw[1],hw[2],hw[3]);
                    *(uint4*)(ah + 16) = make_uint4(hw[4],hw[5],hw[6],hw[7]);
                    *(uint4*)(al)      = make_uint4(lw[0],lw[1],lw[2],lw[3]);
                    *(uint4*)(al + 16) = make_uint4(lw[4],lw[5],lw[6],lw[7]);
                }

                if (pu == 3) {   // orientation features, cols 256..271
                    float ox = xs_[0], oy = xs_[1], oz = xs_[2];
                    const float* q = g_Q + (size_t)sidx * 9;
                    float q0=q[0],q1=q[1],q2=q[2],q3=q[3],q4=q[4],
                          q5=q[5],q6=q[6],q7=q[7],q8=q[8];
                    float fv[12];
                    #pragma unroll
                    for (int a = 0; a < 4; a++) {
                        int da = c_AMAP[a];
                        float px = xd_[da*3+0]-ox, py = xd_[da*3+1]-oy, pz = xd_[da*3+2]-oz;
                        float vx = q0*px + q3*py + q6*pz;
                        float vy = q1*px + q4*py + q7*pz;
                        float vz = q2*px + q5*py + q8*pz;
                        float n = sqrtf(vx*vx + vy*vy + vz*vz);
                        if (n == 0.f) n = 1.f;
                        float r = 1.f / n;
                        fv[a*3+0] = vx*r; fv[a*3+1] = vy*r; fv[a*3+2] = vz*r;
                    }
                    uint32_t hw[8], lw[8];
                    #pragma unroll
                    for (int k = 0; k < 6; k++) {
                        hw[k] = pk2h(fv[2*k], fv[2*k+1]);
                        lw[k] = pk2h(hres(fv[2*k]), hres(fv[2*k+1]));
                    }
                    hw[6] = hw[7] = lw[6] = lw[7] = 0u;
                    char* ah = aHb + el*ROWB + 512;
                    char* al = aLb + el*ROWB + 512;
                    *(uint4*)(ah)      = make_uint4(hw[0],hw[1],hw[2],hw[3]);
                    *(uint4*)(ah + 16) = make_uint4(hw[4],hw[5],hw[6],hw[7]);
                    *(uint4*)(al)      = make_uint4(lw[0],lw[1],lw[2],lw[3]);
                    *(uint4*)(al + 16) = make_uint4(lw[4],lw[5],lw[6],lw[7]);
                }
            }
            BAR_SYNC(6, 256);        // drain producer STS (visibility)
            BAR_ARRIVE(1 + s, 512);  // signal full
        }
    }
}

// ------------------------------- launcher ----------------------------------
extern "C" void kernel_launch(void* const* d_in, const int* in_sizes, int n_in,
                              void* d_out, int out_size)
{
    const float* X   = (const float*)d_in[0];
    const int*   Ein = (const int*)d_in[1];
    const int*   Eex = (const int*)d_in[2];
    const float* nW  = (const float*)d_in[3];
    const float* nb  = (const float*)d_in[4];
    const float* eW  = (const float*)d_in[5];
    const float* eb  = (const float*)d_in[6];
    const float* gn  = (const float*)d_in[7];
    const float* bn  = (const float*)d_in[8];
    const float* ge  = (const float*)d_in[9];
    const float* be  = (const float*)d_in[10];

    int N = in_sizes[0] / 12;
    int E = in_sizes[1] / 2;
    float* out = (float*)d_out;

    cudaFuncSetAttribute(node_kernel, cudaFuncAttributeMaxDynamicSharedMemorySize,
                         NODE_SMEM_FLOATS * 4);
    cudaFuncSetAttribute(edge_hmma_kernel, cudaFuncAttributeMaxDynamicSharedMemorySize,
                         EDGE_SMEM);

    int sms = 148;
    cudaDeviceGetAttribute(&sms, cudaDevAttrMultiProcessorCount, 0);

    q_kernel<<<(N + 127) / 128, 128>>>(X, N);
    node_kernel<<<512, 128, NODE_SMEM_FLOATS * 4>>>(X, nW, nb, gn, bn, out, N);

    float* out_in = out + (size_t)N * 128;
    float* out_ex = out_in + (size_t)E * 128;
    edge_hmma_kernel<<<sms, 512, EDGE_SMEM>>>(X, Ein, Eex, E, eW, eb, ge, be,
                                              out_in, out_ex);
}

// round 11
// speedup vs baseline: 2.1053x; 1.1631x over previous
#include <cuda_runtime.h>
#include <cuda_fp16.h>
#include <cstdint>

// ===========================================================================
// Protein graph featurization.
//   h_V    = LN(node_rbf(96) @ node_W^T + node_b)        [N,128]
//   h_E_*  = LN(edge_feats(268) @ edge_W^T + edge_b)     [E,128] x2
// Edge GEMM on HMMA mma.sync m16n8k16 fp16, SINGLE pass (A and B each
// rounded once to fp16: rel err ~3e-4 < 1e-3). Producer/consumer warp
// specialization, 64-edge tiles, A double-buffered.
// ===========================================================================

#define QMAX 131072
__device__ float g_Q[QMAX * 9];   // per-node frame: b1(3), n0(3), b2(3)

__device__ __constant__ int c_NA[6]  = {1, 1, 1, 0, 0, 3};
__device__ __constant__ int c_NB[6]  = {0, 2, 3, 2, 3, 2};
__device__ __constant__ int c_EA[16] = {1,1,2,1,0,1,3,2,2,0,2,3,0,0,3,3};
__device__ __constant__ int c_EB[16] = {1,2,1,0,1,3,1,2,0,2,3,2,0,3,0,3};
__device__ __constant__ int c_AMAP[4] = {1, 0, 2, 3};

// ------------------------------ helpers ------------------------------------
__device__ __forceinline__ uint32_t smem_to_u32(const void* p) {
    uint32_t a;
    asm("{ .reg .u64 t; cvta.to.shared.u64 t, %1; cvt.u32.u64 %0, t; }"
        : "=r"(a) : "l"(p));
    return a;
}
__device__ __forceinline__ void ldsm4(uint32_t* r, uint32_t addr) {
    asm volatile("ldmatrix.sync.aligned.m8n8.x4.shared.b16 {%0,%1,%2,%3}, [%4];"
        : "=r"(r[0]), "=r"(r[1]), "=r"(r[2]), "=r"(r[3]) : "r"(addr));
}
__device__ __forceinline__ void mma_f16(float* d, const uint32_t* a,
                                        uint32_t b0, uint32_t b1) {
    asm volatile("mma.sync.aligned.m16n8k16.row.col.f32.f16.f16.f32 "
        "{%0,%1,%2,%3}, {%4,%5,%6,%7}, {%8,%9}, {%0,%1,%2,%3};"
        : "+f"(d[0]), "+f"(d[1]), "+f"(d[2]), "+f"(d[3])
        : "r"(a[0]), "r"(a[1]), "r"(a[2]), "r"(a[3]), "r"(b0), "r"(b1));
}
#define BAR_SYNC(id, cnt) \
    asm volatile("bar.sync %0, %1;" :: "r"(id), "r"(cnt) : "memory")
#define BAR_ARRIVE(id, cnt) \
    asm volatile("bar.arrive %0, %1;" :: "r"(id), "r"(cnt) : "memory")

__device__ __forceinline__ uint32_t pk2h(float a, float b) {
    __half2 h = __floats2half2_rn(a, b);
    return *(uint32_t*)&h;
}

// --------------------------- frame precompute ------------------------------
__global__ void q_kernel(const float* __restrict__ X, int N) {
    int i = blockIdx.x * blockDim.x + threadIdx.x;
    if (i >= N) return;
    float* q = &g_Q[i * 9];
    if (i == N - 1) {
        #pragma unroll
        for (int j = 0; j < 9; j++) q[j] = 0.f;
        return;
    }
    const float* x = X + (size_t)i * 12;
    float ax = x[3] - x[0], ay = x[4] - x[1], az = x[5] - x[2];
    float n = sqrtf(ax*ax + ay*ay + az*az); if (n == 0.f) n = 1.f;
    float r = 1.f / n;
    float u0x = ax*r, u0y = ay*r, u0z = az*r;
    float bx = x[6] - x[3], by = x[7] - x[4], bz = x[8] - x[5];
    n = sqrtf(bx*bx + by*by + bz*bz); if (n == 0.f) n = 1.f;
    r = 1.f / n;
    float u1x = bx*r, u1y = by*r, u1z = bz*r;
    float cx = u0y*u1z - u0z*u1y, cy = u0z*u1x - u0x*u1z, cz = u0x*u1y - u0y*u1x;
    n = sqrtf(cx*cx + cy*cy + cz*cz); if (n == 0.f) n = 1.f;
    r = 1.f / n;
    float n0x = cx*r, n0y = cy*r, n0z = cz*r;
    float dx = u0x-u1x, dy = u0y-u1y, dz = u0z-u1z;
    n = sqrtf(dx*dx + dy*dy + dz*dz); if (n == 0.f) n = 1.f;
    r = 1.f / n;
    float b1x = dx*r, b1y = dy*r, b1z = dz*r;
    q[0]=b1x; q[1]=b1y; q[2]=b1z;
    q[3]=n0x; q[4]=n0y; q[5]=n0z;
    q[6]=b1y*n0z-b1z*n0y; q[7]=b1z*n0x-b1x*n0z; q[8]=b1x*n0y-b1y*n0x;
}

// ------------------------------ node kernel --------------------------------
#define NODE_SMEM_FLOATS (96 * 128 + 96 + 12 + 8)
__global__ __launch_bounds__(128) void node_kernel(
    const float* __restrict__ X, const float* __restrict__ W,
    const float* __restrict__ b, const float* __restrict__ gain,
    const float* __restrict__ bias, float* __restrict__ out, int N)
{
    extern __shared__ float sm[];
    float* Wsh  = sm;
    float* feat = Wsh + 96 * 128;
    float* xsh  = feat + 96;
    float* red  = xsh + 12;
    int t = threadIdx.x;
    for (int i = t; i < 96 * 128; i += 128) {
        int o = i / 96, f = i - o * 96;
        Wsh[f * 128 + o] = W[i];
    }
    float nb = b[t], ng = gain[t], nbi = bias[t];
    __syncthreads();
    for (int i = blockIdx.x; i < N; i += gridDim.x) {
        if (t < 12) xsh[t] = X[(size_t)i * 12 + t];
        __syncthreads();
        if (t < 96) {
            int p = t >> 4, k = t & 15;
            int a = c_NA[p], bb = c_NB[p];
            float dx = xsh[a*3+0]-xsh[bb*3+0], dy = xsh[a*3+1]-xsh[bb*3+1], dz = xsh[a*3+2]-xsh[bb*3+2];
            float D = sqrtf(dx*dx + dy*dy + dz*dz + 1e-6f);
            float z = (D - (float)k * (20.f/15.f)) * 0.8f;
            feat[t] = __expf(-z * z);
        }
        __syncthreads();
        float acc = nb;
        #pragma unroll 8
        for (int f = 0; f < 96; f++) acc += feat[f] * Wsh[f * 128 + t];
        float s = acc, sq = acc * acc;
        #pragma unroll
        for (int off = 16; off; off >>= 1) {
            s  += __shfl_down_sync(0xffffffffu, s, off);
            sq += __shfl_down_sync(0xffffffffu, sq, off);
        }
        if ((t & 31) == 0) { red[(t>>5)*2] = s; red[(t>>5)*2+1] = sq; }
        __syncthreads();
        float S  = red[0]+red[2]+red[4]+red[6];
        float Sq = red[1]+red[3]+red[5]+red[7];
        float mu = S * (1.f/128.f);
        float sig = sqrtf((Sq - S*mu) * (1.f/127.f) + 1e-6f);
        out[(size_t)i * 128 + t] = ng * (acc - mu) / (sig + 1e-6f) + nbi;
        __syncthreads();
    }
}

// ------------------- edge HMMA kernel (fp16 single-pass) -------------------
// 512 thr: warps 0-7 consumers (warp = 16 edges x 64 cols), warps 8-15
// producers. Tile = 64 edges, A fp16 double-buffered, B fp16.
// Row stride 560B = 35*16B (35%8=3 -> ldmatrix conflict-free).
#define ROWB      560
#define OFF_PAR   0                          // eb/gain/bias: 1536 B
#define OFF_RED   1536                       // 2 x (64 e x 2 halves x float2)
#define RED_STAGE 1024
#define OFF_BHI   (OFF_RED + 2*RED_STAGE)    // 3584
#define OFF_A     (OFF_BHI + 128*ROWB)       // 75264
#define A_STAGE   (64*ROWB)                  // 35840
#define EDGE_SMEM (OFF_A + 2*A_STAGE)        // 146944
// named barriers: 1,2 = full[s]; 3,4 = empty[s]; 5 = consumers; 6 = producers

__global__ __launch_bounds__(512, 1)
void edge_hmma_kernel(const float* __restrict__ X,
                      const int* __restrict__ idx1, const int* __restrict__ idx2,
                      int E, const float* __restrict__ W,
                      const float* __restrict__ eb, const float* __restrict__ egain,
                      const float* __restrict__ ebias,
                      float* __restrict__ out1, float* __restrict__ out2)
{
    extern __shared__ char smem[];
    uint32_t sb = smem_to_u32(smem);
    int t = threadIdx.x;

    // ---- one-time staging: params + W -> fp16 in SMEM ----
    if (t < 128) {
        ((float*)(smem + OFF_PAR))[t]       = eb[t];
        ((float*)(smem + OFF_PAR))[128 + t] = egain[t];
        ((float*)(smem + OFF_PAR))[256 + t] = ebias[t];
    }
    for (int i = t; i < 128 * 268; i += 512) {
        int r = i / 268, k = i - r * 268;
        *(__half*)(smem + OFF_BHI + r*ROWB + k*2) = __float2half_rn(W[i]);
    }
    for (int i = t; i < 128 * 4; i += 512) {       // zero W cols 268..271
        int r = i >> 2, c = 268 + (i & 3);
        *(uint16_t*)(smem + OFF_BHI + r*ROWB + c*2) = 0;
    }
    __syncthreads();

    const int ntiles  = (E + 63) >> 6;
    const int ntiles2 = ntiles * 2;
    const int grid    = gridDim.x;

    if (t < 256) {
        // =========================== CONSUMER ===========================
        int wid = t >> 5, lane = t & 31;
        int egrp = wid & 3, nhalf = wid >> 2;
        int t4 = lane & 3, g = lane >> 2;
        uint32_t aOff = (uint32_t)(egrp*16 + (lane & 15)) * ROWB
                      + ((lane & 16) ? 16u : 0u);
        uint32_t bRow = (uint32_t)(nhalf*64 + ((lane & 7) | ((lane & 16) >> 1)));
        uint32_t bOff = bRow * ROWB + ((lane & 8) ? 16u : 0u);
        uint32_t bHiA = sb + OFF_BHI + bOff;

        int it = 0;
        for (int tile = blockIdx.x; tile < ntiles2; tile += grid, it++) {
            int s = it & 1;
            bool ex = tile >= ntiles;
            int ebase = (ex ? tile - ntiles : tile) * 64;
            float* outp = ex ? out2 : out1;
            uint32_t aHi = sb + OFF_A + s*A_STAGE + aOff;

            BAR_SYNC(1 + s, 512);                     // wait full

            float acc[8][4];
            #pragma unroll
            for (int n = 0; n < 8; n++)
                acc[n][0] = acc[n][1] = acc[n][2] = acc[n][3] = 0.f;

            #pragma unroll 1
            for (int ks = 0; ks < 17; ks++) {
                uint32_t ko = (uint32_t)ks * 32;
                uint32_t aH[4], bF[4][4];
                ldsm4(aH, aHi + ko);
                #pragma unroll
                for (int np = 0; np < 4; np++)
                    ldsm4(bF[np], bHiA + np*(16*ROWB) + ko);
                #pragma unroll
                for (int n = 0; n < 8; n++)
                    mma_f16(acc[n], aH, bF[n>>1][(n&1)*2], bF[n>>1][(n&1)*2+1]);
            }
            BAR_ARRIVE(3 + s, 512);                   // signal empty

            // ---- epilogue: bias + LN (cross-half) + store ----
            int e0 = egrp*16 + g, e1 = e0 + 8;
            float S0=0, Q0=0, S1=0, Q1=0;
            #pragma unroll
            for (int n = 0; n < 8; n++) {
                int col = nhalf*64 + n*8 + t4*2;
                float2 b2 = *(const float2*)(smem + OFF_PAR + col*4);
                acc[n][0] += b2.x; acc[n][1] += b2.y;
                acc[n][2] += b2.x; acc[n][3] += b2.y;
                S0 += acc[n][0] + acc[n][1];
                Q0 += acc[n][0]*acc[n][0] + acc[n][1]*acc[n][1];
                S1 += acc[n][2] + acc[n][3];
                Q1 += acc[n][2]*acc[n][2] + acc[n][3]*acc[n][3];
            }
            #pragma unroll
            for (int off = 1; off <= 2; off <<= 1) {
                S0 += __shfl_xor_sync(0xffffffffu, S0, off);
                Q0 += __shfl_xor_sync(0xffffffffu, Q0, off);
                S1 += __shfl_xor_sync(0xffffffffu, S1, off);
                Q1 += __shfl_xor_sync(0xffffffffu, Q1, off);
            }
            float2* red = (float2*)(smem + OFF_RED + s*RED_STAGE);
            if (t4 == 0) {
                red[e0*2 + nhalf] = make_float2(S0, Q0);
                red[e1*2 + nhalf] = make_float2(S1, Q1);
            }
            BAR_SYNC(5, 256);
            float2 ra = red[e0*2], rb = red[e0*2+1];
            float St0 = ra.x + rb.x, Qt0 = ra.y + rb.y;
            float2 rc = red[e1*2], rd = red[e1*2+1];
            float St1 = rc.x + rd.x, Qt1 = rc.y + rd.y;
            float mu0 = St0 * (1.f/128.f);
            float rs0 = 1.f / (sqrtf((Qt0 - St0*mu0) * (1.f/127.f) + 1e-6f) + 1e-6f);
            float mu1 = St1 * (1.f/128.f);
            float rs1 = 1.f / (sqrtf((Qt1 - St1*mu1) * (1.f/127.f) + 1e-6f) + 1e-6f);

            int ge0 = ebase + e0, ge1 = ebase + e1;
            float* op0 = outp + (size_t)ge0 * 128;
            float* op1 = outp + (size_t)ge1 * 128;
            #pragma unroll
            for (int n = 0; n < 8; n++) {
                int col = nhalf*64 + n*8 + t4*2;
                float2 gn2 = *(const float2*)(smem + OFF_PAR + 512 + col*4);
                float2 bs2 = *(const float2*)(smem + OFF_PAR + 1024 + col*4);
                if (ge0 < E) {
                    float2 o;
                    o.x = gn2.x * (acc[n][0] - mu0) * rs0 + bs2.x;
                    o.y = gn2.y * (acc[n][1] - mu0) * rs0 + bs2.y;
                    __stcs((float2*)(op0 + col), o);
                }
                if (ge1 < E) {
                    float2 o;
                    o.x = gn2.x * (acc[n][2] - mu1) * rs1 + bs2.x;
                    o.y = gn2.y * (acc[n][3] - mu1) * rs1 + bs2.y;
                    __stcs((float2*)(op1 + col), o);
                }
            }
        }
    } else {
        // =========================== PRODUCER ===========================
        int t2 = t - 256;
        int el = t2 & 63;        // edge within tile
        int pu = t2 >> 6;        // pair quarter: pairs pu*4 .. pu*4+3

        int it = 0;
        for (int tile = blockIdx.x; tile < ntiles2; tile += grid, it++) {
            int s = it & 1;
            bool ex = tile >= ntiles;
            int ebase = (ex ? tile - ntiles : tile) * 64;
            const int* ix = ex ? idx2 : idx1;
            char* aHb = smem + OFF_A + s*A_STAGE;

            if (it >= 2) BAR_SYNC(3 + s, 512);         // wait empty

            int ge = ebase + el;
            if (ge < E) {
                int sidx = ix[ge], didx = ix[E + ge];
                const float* xs_ = X + (size_t)sidx * 12;
                const float* xd_ = X + (size_t)didx * 12;

                #pragma unroll
                for (int j = 0; j < 4; j++) {
                    int p = pu * 4 + j;
                    const float* xa = xs_ + c_EA[p] * 3;
                    const float* xb = xd_ + c_EB[p] * 3;
                    float dx = xa[0]-xb[0], dy = xa[1]-xb[1], dz = xa[2]-xb[2];
                    float D = sqrtf(dx*dx + dy*dy + dz*dz + 1e-6f);
                    float f[16];
                    #pragma unroll
                    for (int k = 0; k < 16; k++) {
                        float z = (D - (float)k * (20.f/15.f)) * 0.8f;
                        f[k] = __expf(-z * z);
                    }
                    uint32_t hw[8];
                    #pragma unroll
                    for (int k = 0; k < 8; k++)
                        hw[k] = pk2h(f[2*k], f[2*k+1]);
                    char* ah = aHb + el*ROWB + p*32;
                    *(uint4*)(ah)      = make_uint4(hw[0],hw[1],hw[2],hw[3]);
                    *(uint4*)(ah + 16) = make_uint4(hw[4],hw[5],hw[6],hw[7]);
                }

                if (pu == 3) {   // orientation features, cols 256..271
                    float ox = xs_[0], oy = xs_[1], oz = xs_[2];
                    const float* q = g_Q + (size_t)sidx * 9;
                    float q0=q[0],q1=q[1],q2=q[2],q3=q[3],q4=q[4],
                          q5=q[5],q6=q[6],q7=q[7],q8=q[8];
                    float fv[12];
                    #pragma unroll
                    for (int a = 0; a < 4; a++) {
                        int da = c_AMAP[a];
                        float px = xd_[da*3+0]-ox, py = xd_[da*3+1]-oy, pz = xd_[da*3+2]-oz;
                        float vx = q0*px + q3*py + q6*pz;
                        float vy = q1*px + q4*py + q7*pz;
                        float vz = q2*px + q5*py + q8*pz;
                        float n = sqrtf(vx*vx + vy*vy + vz*vz);
                        if (n == 0.f) n = 1.f;
                        float r = 1.f / n;
                        fv[a*3+0] = vx*r; fv[a*3+1] = vy*r; fv[a*3+2] = vz*r;
                    }
                    uint32_t hw[8];
                    #pragma unroll
                    for (int k = 0; k < 6; k++)
                        hw[k] = pk2h(fv[2*k], fv[2*k+1]);
                    hw[6] = hw[7] = 0u;
                    char* ah = aHb + el*ROWB + 512;
                    *(uint4*)(ah)      = make_uint4(hw[0],hw[1],hw[2],hw[3]);
                    *(uint4*)(ah + 16) = make_uint4(hw[4],hw[5],hw[6],hw[7]);
                }
            }
            BAR_SYNC(6, 256);        // drain producer STS (visibility)
            BAR_ARRIVE(1 + s, 512);  // signal full
        }
    }
}

// ------------------------------- launcher ----------------------------------
extern "C" void kernel_launch(void* const* d_in, const int* in_sizes, int n_in,
                              void* d_out, int out_size)
{
    const float* X   = (const float*)d_in[0];
    const int*   Ein = (const int*)d_in[1];
    const int*   Eex = (const int*)d_in[2];
    const float* nW  = (const float*)d_in[3];
    const float* nb  = (const float*)d_in[4];
    const float* eW  = (const float*)d_in[5];
    const float* eb  = (const float*)d_in[6];
    const float* gn  = (const float*)d_in[7];
    const float* bn  = (const float*)d_in[8];
    const float* ge  = (const float*)d_in[9];
    const float* be  = (const float*)d_in[10];

    int N = in_sizes[0] / 12;
    int E = in_sizes[1] / 2;
    float* out = (float*)d_out;

    cudaFuncSetAttribute(node_kernel, cudaFuncAttributeMaxDynamicSharedMemorySize,
                         NODE_SMEM_FLOATS * 4);
    cudaFuncSetAttribute(edge_hmma_kernel, cudaFuncAttributeMaxDynamicSharedMemorySize,
                         EDGE_SMEM);

    int sms = 148;
    cudaDeviceGetAttribute(&sms, cudaDevAttrMultiProcessorCount, 0);

    q_kernel<<<(N + 127) / 128, 128>>>(X, N);
    node_kernel<<<512, 128, NODE_SMEM_FLOATS * 4>>>(X, nW, nb, gn, bn, out, N);

    float* out_in = out + (size_t)N * 128;
    float* out_ex = out_in + (size_t)E * 128;
    edge_hmma_kernel<<<sms, 512, EDGE_SMEM>>>(X, Ein, Eex, E, eW, eb, ge, be,
                                              out_in, out_ex);
}

// round 16
// speedup vs baseline: 2.8453x; 1.3515x over previous
#include <cuda_runtime.h>
#include <cuda_fp16.h>
#include <cstdint>

// ===========================================================================
// Protein graph featurization.
//   h_V    = LN(node_rbf(96) @ node_W^T + node_b)        [N,128]
//   h_E_*  = LN(edge_feats(268) @ edge_W^T + edge_b)     [E,128] x2
// Both GEMMs on HMMA mma.sync m16n8k16 fp16 (single rounding, rel ~3e-4).
// Producer/consumer warp specialization; edge A tiles triple-buffered.
// ===========================================================================

#define QMAX 131072
__device__ float g_Q[QMAX * 9];   // per-node frame: b1(3), n0(3), b2(3)

__device__ __constant__ int c_NA[6]  = {1, 1, 1, 0, 0, 3};
__device__ __constant__ int c_NB[6]  = {0, 2, 3, 2, 3, 2};
__device__ __constant__ int c_EA[16] = {1,1,2,1,0,1,3,2,2,0,2,3,0,0,3,3};
__device__ __constant__ int c_EB[16] = {1,2,1,0,1,3,1,2,0,2,3,2,0,3,0,3};
__device__ __constant__ int c_AMAP[4] = {1, 0, 2, 3};

// ------------------------------ helpers ------------------------------------
__device__ __forceinline__ uint32_t smem_to_u32(const void* p) {
    uint32_t a;
    asm("{ .reg .u64 t; cvta.to.shared.u64 t, %1; cvt.u32.u64 %0, t; }"
        : "=r"(a) : "l"(p));
    return a;
}
__device__ __forceinline__ void ldsm4(uint32_t* r, uint32_t addr) {
    asm volatile("ldmatrix.sync.aligned.m8n8.x4.shared.b16 {%0,%1,%2,%3}, [%4];"
        : "=r"(r[0]), "=r"(r[1]), "=r"(r[2]), "=r"(r[3]) : "r"(addr));
}
__device__ __forceinline__ void mma_f16(float* d, const uint32_t* a,
                                        uint32_t b0, uint32_t b1) {
    asm volatile("mma.sync.aligned.m16n8k16.row.col.f32.f16.f16.f32 "
        "{%0,%1,%2,%3}, {%4,%5,%6,%7}, {%8,%9}, {%0,%1,%2,%3};"
        : "+f"(d[0]), "+f"(d[1]), "+f"(d[2]), "+f"(d[3])
        : "r"(a[0]), "r"(a[1]), "r"(a[2]), "r"(a[3]), "r"(b0), "r"(b1));
}
#define BAR_SYNC(id, cnt) \
    asm volatile("bar.sync %0, %1;" :: "r"(id), "r"(cnt) : "memory")
#define BAR_ARRIVE(id, cnt) \
    asm volatile("bar.arrive %0, %1;" :: "r"(id), "r"(cnt) : "memory")

__device__ __forceinline__ uint32_t pk2h(float a, float b) {
    __half2 h = __floats2half2_rn(a, b);
    return *(uint32_t*)&h;
}

// --------------------------- frame precompute ------------------------------
__global__ void q_kernel(const float* __restrict__ X, int N) {
    int i = blockIdx.x * blockDim.x + threadIdx.x;
    if (i >= N) return;
    float* q = &g_Q[i * 9];
    if (i == N - 1) {
        #pragma unroll
        for (int j = 0; j < 9; j++) q[j] = 0.f;
        return;
    }
    const float* x = X + (size_t)i * 12;
    float ax = x[3] - x[0], ay = x[4] - x[1], az = x[5] - x[2];
    float n = sqrtf(ax*ax + ay*ay + az*az); if (n == 0.f) n = 1.f;
    float r = 1.f / n;
    float u0x = ax*r, u0y = ay*r, u0z = az*r;
    float bx = x[6] - x[3], by = x[7] - x[4], bz = x[8] - x[5];
    n = sqrtf(bx*bx + by*by + bz*bz); if (n == 0.f) n = 1.f;
    r = 1.f / n;
    float u1x = bx*r, u1y = by*r, u1z = bz*r;
    float cx = u0y*u1z - u0z*u1y, cy = u0z*u1x - u0x*u1z, cz = u0x*u1y - u0y*u1x;
    n = sqrtf(cx*cx + cy*cy + cz*cz); if (n == 0.f) n = 1.f;
    r = 1.f / n;
    float n0x = cx*r, n0y = cy*r, n0z = cz*r;
    float dx = u0x-u1x, dy = u0y-u1y, dz = u0z-u1z;
    n = sqrtf(dx*dx + dy*dy + dz*dz); if (n == 0.f) n = 1.f;
    r = 1.f / n;
    float b1x = dx*r, b1y = dy*r, b1z = dz*r;
    q[0]=b1x; q[1]=b1y; q[2]=b1z;
    q[3]=n0x; q[4]=n0y; q[5]=n0z;
    q[6]=b1y*n0z-b1z*n0y; q[7]=b1z*n0x-b1x*n0z; q[8]=b1x*n0y-b1y*n0x;
}

// ----------------------- node HMMA kernel (K=96) ---------------------------
// Same producer/consumer skeleton as edge kernel; tile = 64 nodes,
// K = 96 (6 k-steps), row stride 208B = 13*16B (odd -> ldsm conflict-free).
// Small smem (56.8KB) -> multiple CTAs/SM.
#define NROWB     208
#define N_OFF_PAR 0                           // b/gain/bias: 1536 B
#define N_OFF_RED 1536                        // 2 x 1024
#define N_OFF_B   (N_OFF_RED + 2048)          // 3584
#define N_OFF_A   (N_OFF_B + 128*NROWB)       // 30208
#define N_A_STAGE (64*NROWB)                  // 13312
#define NODE_SMEM (N_OFF_A + 2*N_A_STAGE)     // 56832

__global__ __launch_bounds__(512)
void node_hmma_kernel(const float* __restrict__ X, int N,
                      const float* __restrict__ W, const float* __restrict__ nb,
                      const float* __restrict__ ngain, const float* __restrict__ nbias,
                      float* __restrict__ out)
{
    extern __shared__ char smem[];
    uint32_t sb = smem_to_u32(smem);
    int t = threadIdx.x;

    if (t < 128) {
        ((float*)(smem + N_OFF_PAR))[t]       = nb[t];
        ((float*)(smem + N_OFF_PAR))[128 + t] = ngain[t];
        ((float*)(smem + N_OFF_PAR))[256 + t] = nbias[t];
    }
    for (int i = t; i < 128 * 96; i += 512) {
        int r = i / 96, k = i - r * 96;
        *(__half*)(smem + N_OFF_B + r*NROWB + k*2) = __float2half_rn(W[i]);
    }
    __syncthreads();

    const int ntiles = (N + 63) >> 6;
    const int grid   = gridDim.x;

    if (t < 256) {
        // ------------------------- CONSUMER -------------------------
        int wid = t >> 5, lane = t & 31;
        int egrp = wid & 3, nhalf = wid >> 2;
        int t4 = lane & 3, g = lane >> 2;
        uint32_t aOff = (uint32_t)(egrp*16 + (lane & 15)) * NROWB
                      + ((lane & 16) ? 16u : 0u);
        uint32_t bRow = (uint32_t)(nhalf*64 + ((lane & 7) | ((lane & 16) >> 1)));
        uint32_t bOff = bRow * NROWB + ((lane & 8) ? 16u : 0u);
        uint32_t bA = sb + N_OFF_B + bOff;

        int it = 0;
        for (int tile = blockIdx.x; tile < ntiles; tile += grid, it++) {
            int s = it & 1;
            int nbase = tile * 64;
            uint32_t aA = sb + N_OFF_A + s*N_A_STAGE + aOff;

            BAR_SYNC(1 + s, 512);

            float acc[8][4];
            #pragma unroll
            for (int n = 0; n < 8; n++)
                acc[n][0] = acc[n][1] = acc[n][2] = acc[n][3] = 0.f;

            #pragma unroll
            for (int ks = 0; ks < 6; ks++) {
                uint32_t ko = (uint32_t)ks * 32;
                uint32_t aH[4], bF[4][4];
                ldsm4(aH, aA + ko);
                #pragma unroll
                for (int np = 0; np < 4; np++)
                    ldsm4(bF[np], bA + np*(16*NROWB) + ko);
                #pragma unroll
                for (int n = 0; n < 8; n++)
                    mma_f16(acc[n], aH, bF[n>>1][(n&1)*2], bF[n>>1][(n&1)*2+1]);
            }
            BAR_ARRIVE(3 + s, 512);

            int e0 = egrp*16 + g, e1 = e0 + 8;
            float S0=0, Q0=0, S1=0, Q1=0;
            #pragma unroll
            for (int n = 0; n < 8; n++) {
                int col = nhalf*64 + n*8 + t4*2;
                float2 b2 = *(const float2*)(smem + N_OFF_PAR + col*4);
                acc[n][0] += b2.x; acc[n][1] += b2.y;
                acc[n][2] += b2.x; acc[n][3] += b2.y;
                S0 += acc[n][0] + acc[n][1];
                Q0 += acc[n][0]*acc[n][0] + acc[n][1]*acc[n][1];
                S1 += acc[n][2] + acc[n][3];
                Q1 += acc[n][2]*acc[n][2] + acc[n][3]*acc[n][3];
            }
            #pragma unroll
            for (int off = 1; off <= 2; off <<= 1) {
                S0 += __shfl_xor_sync(0xffffffffu, S0, off);
                Q0 += __shfl_xor_sync(0xffffffffu, Q0, off);
                S1 += __shfl_xor_sync(0xffffffffu, S1, off);
                Q1 += __shfl_xor_sync(0xffffffffu, Q1, off);
            }
            float2* red = (float2*)(smem + N_OFF_RED + s*1024);
            if (t4 == 0) {
                red[e0*2 + nhalf] = make_float2(S0, Q0);
                red[e1*2 + nhalf] = make_float2(S1, Q1);
            }
            BAR_SYNC(5, 256);
            float2 ra = red[e0*2], rb = red[e0*2+1];
            float St0 = ra.x + rb.x, Qt0 = ra.y + rb.y;
            float2 rc = red[e1*2], rd = red[e1*2+1];
            float St1 = rc.x + rd.x, Qt1 = rc.y + rd.y;
            float mu0 = St0 * (1.f/128.f);
            float rs0 = 1.f / (sqrtf((Qt0 - St0*mu0) * (1.f/127.f) + 1e-6f) + 1e-6f);
            float mu1 = St1 * (1.f/128.f);
            float rs1 = 1.f / (sqrtf((Qt1 - St1*mu1) * (1.f/127.f) + 1e-6f) + 1e-6f);

            int gn0 = nbase + e0, gn1 = nbase + e1;
            float* op0 = out + (size_t)gn0 * 128;
            float* op1 = out + (size_t)gn1 * 128;
            #pragma unroll
            for (int n = 0; n < 8; n++) {
                int col = nhalf*64 + n*8 + t4*2;
                float2 gn2 = *(const float2*)(smem + N_OFF_PAR + 512 + col*4);
                float2 bs2 = *(const float2*)(smem + N_OFF_PAR + 1024 + col*4);
                if (gn0 < N) {
                    float2 o;
                    o.x = gn2.x * (acc[n][0] - mu0) * rs0 + bs2.x;
                    o.y = gn2.y * (acc[n][1] - mu0) * rs0 + bs2.y;
                    __stcs((float2*)(op0 + col), o);
                }
                if (gn1 < N) {
                    float2 o;
                    o.x = gn2.x * (acc[n][2] - mu1) * rs1 + bs2.x;
                    o.y = gn2.y * (acc[n][3] - mu1) * rs1 + bs2.y;
                    __stcs((float2*)(op1 + col), o);
                }
            }
        }
    } else {
        // ------------------------- PRODUCER -------------------------
        int t2 = t - 256;
        int el = t2 & 63;
        int pu = t2 >> 6;        // 0..3; pu<3 handle pairs 2pu, 2pu+1

        int it = 0;
        for (int tile = blockIdx.x; tile < ntiles; tile += grid, it++) {
            int s = it & 1;
            int nbase = tile * 64;
            char* aB = smem + N_OFF_A + s*N_A_STAGE;

            if (it >= 2) BAR_SYNC(3 + s, 512);

            int gn = nbase + el;
            if (gn < N && pu < 3) {
                const float* x = X + (size_t)gn * 12;
                #pragma unroll
                for (int j = 0; j < 2; j++) {
                    int p = pu * 2 + j;
                    int a = c_NA[p], bb = c_NB[p];
                    float dx = x[a*3+0]-x[bb*3+0];
                    float dy = x[a*3+1]-x[bb*3+1];
                    float dz = x[a*3+2]-x[bb*3+2];
                    float D = sqrtf(dx*dx + dy*dy + dz*dz + 1e-6f);
                    float f[16];
                    #pragma unroll
                    for (int k = 0; k < 16; k++) {
                        float z = (D - (float)k * (20.f/15.f)) * 0.8f;
                        f[k] = __expf(-z * z);
                    }
                    uint32_t hw[8];
                    #pragma unroll
                    for (int k = 0; k < 8; k++)
                        hw[k] = pk2h(f[2*k], f[2*k+1]);
                    char* ah = aB + el*NROWB + p*32;
                    *(uint4*)(ah)      = make_uint4(hw[0],hw[1],hw[2],hw[3]);
                    *(uint4*)(ah + 16) = make_uint4(hw[4],hw[5],hw[6],hw[7]);
                }
            }
            BAR_SYNC(6, 256);
            BAR_ARRIVE(1 + s, 512);
        }
    }
}

// ------------------- edge HMMA kernel (fp16, 3 stages) ---------------------
// 512 thr: warps 0-7 consumers (warp = 16 edges x 64 cols), warps 8-15
// producers. Tile = 64 edges, A fp16 TRIPLE-buffered, B fp16.
// Row stride 560B = 35*16B (35%8=3 -> ldmatrix conflict-free).
#define ROWB      560
#define OFF_PAR   0                          // eb/gain/bias: 1536 B
#define OFF_RED   1536                       // 3 x 1024
#define RED_STAGE 1024
#define OFF_BHI   (OFF_RED + 3*RED_STAGE)    // 4608
#define OFF_A     (OFF_BHI + 128*ROWB)       // 76288
#define A_STAGE   (64*ROWB)                  // 35840
#define EDGE_SMEM (OFF_A + 3*A_STAGE)        // 183808
// named barriers: 1..3 full[s]; 4..6 empty[s]; 7 consumers; 8 producers

__global__ __launch_bounds__(512, 1)
void edge_hmma_kernel(const float* __restrict__ X,
                      const int* __restrict__ idx1, const int* __restrict__ idx2,
                      int E, const float* __restrict__ W,
                      const float* __restrict__ eb, const float* __restrict__ egain,
                      const float* __restrict__ ebias,
                      float* __restrict__ out1, float* __restrict__ out2)
{
    extern __shared__ char smem[];
    uint32_t sb = smem_to_u32(smem);
    int t = threadIdx.x;

    // ---- one-time staging: params + W -> fp16 in SMEM ----
    if (t < 128) {
        ((float*)(smem + OFF_PAR))[t]       = eb[t];
        ((float*)(smem + OFF_PAR))[128 + t] = egain[t];
        ((float*)(smem + OFF_PAR))[256 + t] = ebias[t];
    }
    for (int i = t; i < 128 * 268; i += 512) {
        int r = i / 268, k = i - r * 268;
        *(__half*)(smem + OFF_BHI + r*ROWB + k*2) = __float2half_rn(W[i]);
    }
    for (int i = t; i < 128 * 4; i += 512) {       // zero W cols 268..271
        int r = i >> 2, c = 268 + (i & 3);
        *(uint16_t*)(smem + OFF_BHI + r*ROWB + c*2) = 0;
    }
    __syncthreads();

    const int ntiles  = (E + 63) >> 6;
    const int ntiles2 = ntiles * 2;
    const int grid    = gridDim.x;

    if (t < 256) {
        // =========================== CONSUMER ===========================
        int wid = t >> 5, lane = t & 31;
        int egrp = wid & 3, nhalf = wid >> 2;
        int t4 = lane & 3, g = lane >> 2;
        uint32_t aOff = (uint32_t)(egrp*16 + (lane & 15)) * ROWB
                      + ((lane & 16) ? 16u : 0u);
        uint32_t bRow = (uint32_t)(nhalf*64 + ((lane & 7) | ((lane & 16) >> 1)));
        uint32_t bOff = bRow * ROWB + ((lane & 8) ? 16u : 0u);
        uint32_t bHiA = sb + OFF_BHI + bOff;

        int it = 0;
        for (int tile = blockIdx.x; tile < ntiles2; tile += grid, it++) {
            int s = it % 3;
            bool ex = tile >= ntiles;
            int ebase = (ex ? tile - ntiles : tile) * 64;
            float* outp = ex ? out2 : out1;
            uint32_t aHi = sb + OFF_A + s*A_STAGE + aOff;

            BAR_SYNC(1 + s, 512);                     // wait full

            float acc[8][4];
            #pragma unroll
            for (int n = 0; n < 8; n++)
                acc[n][0] = acc[n][1] = acc[n][2] = acc[n][3] = 0.f;

            #pragma unroll 1
            for (int ks = 0; ks < 17; ks++) {
                uint32_t ko = (uint32_t)ks * 32;
                uint32_t aH[4], bF[4][4];
                ldsm4(aH, aHi + ko);
                #pragma unroll
                for (int np = 0; np < 4; np++)
                    ldsm4(bF[np], bHiA + np*(16*ROWB) + ko);
                #pragma unroll
                for (int n = 0; n < 8; n++)
                    mma_f16(acc[n], aH, bF[n>>1][(n&1)*2], bF[n>>1][(n&1)*2+1]);
            }
            BAR_ARRIVE(4 + s, 512);                   // signal empty

            // ---- epilogue: bias + LN (cross-half) + store ----
            int e0 = egrp*16 + g, e1 = e0 + 8;
            float S0=0, Q0=0, S1=0, Q1=0;
            #pragma unroll
            for (int n = 0; n < 8; n++) {
                int col = nhalf*64 + n*8 + t4*2;
                float2 b2 = *(const float2*)(smem + OFF_PAR + col*4);
                acc[n][0] += b2.x; acc[n][1] += b2.y;
                acc[n][2] += b2.x; acc[n][3] += b2.y;
                S0 += acc[n][0] + acc[n][1];
                Q0 += acc[n][0]*acc[n][0] + acc[n][1]*acc[n][1];
                S1 += acc[n][2] + acc[n][3];
                Q1 += acc[n][2]*acc[n][2] + acc[n][3]*acc[n][3];
            }
            #pragma unroll
            for (int off = 1; off <= 2; off <<= 1) {
                S0 += __shfl_xor_sync(0xffffffffu, S0, off);
                Q0 += __shfl_xor_sync(0xffffffffu, Q0, off);
                S1 += __shfl_xor_sync(0xffffffffu, S1, off);
                Q1 += __shfl_xor_sync(0xffffffffu, Q1, off);
            }
            float2* red = (float2*)(smem + OFF_RED + s*RED_STAGE);
            if (t4 == 0) {
                red[e0*2 + nhalf] = make_float2(S0, Q0);
                red[e1*2 + nhalf] = make_float2(S1, Q1);
            }
            BAR_SYNC(7, 256);
            float2 ra = red[e0*2], rb = red[e0*2+1];
            float St0 = ra.x + rb.x, Qt0 = ra.y + rb.y;
            float2 rc = red[e1*2], rd = red[e1*2+1];
            float St1 = rc.x + rd.x, Qt1 = rc.y + rd.y;
            float mu0 = St0 * (1.f/128.f);
            float rs0 = 1.f / (sqrtf((Qt0 - St0*mu0) * (1.f/127.f) + 1e-6f) + 1e-6f);
            float mu1 = St1 * (1.f/128.f);
            float rs1 = 1.f / (sqrtf((Qt1 - St1*mu1) * (1.f/127.f) + 1e-6f) + 1e-6f);

            int ge0 = ebase + e0, ge1 = ebase + e1;
            float* op0 = outp + (size_t)ge0 * 128;
            float* op1 = outp + (size_t)ge1 * 128;
            #pragma unroll
            for (int n = 0; n < 8; n++) {
                int col = nhalf*64 + n*8 + t4*2;
                float2 gn2 = *(const float2*)(smem + OFF_PAR + 512 + col*4);
                float2 bs2 = *(const float2*)(smem + OFF_PAR + 1024 + col*4);
                if (ge0 < E) {
                    float2 o;
                    o.x = gn2.x * (acc[n][0] - mu0) * rs0 + bs2.x;
                    o.y = gn2.y * (acc[n][1] - mu0) * rs0 + bs2.y;
                    __stcs((float2*)(op0 + col), o);
                }
                if (ge1 < E) {
                    float2 o;
                    o.x = gn2.x * (acc[n][2] - mu1) * rs1 + bs2.x;
                    o.y = gn2.y * (acc[n][3] - mu1) * rs1 + bs2.y;
                    __stcs((float2*)(op1 + col), o);
                }
            }
        }
    } else {
        // =========================== PRODUCER ===========================
        int t2 = t - 256;
        int el = t2 & 63;        // edge within tile
        int pu = t2 >> 6;        // pair quarter: pairs pu*4 .. pu*4+3

        int it = 0;
        for (int tile = blockIdx.x; tile < ntiles2; tile += grid, it++) {
            int s = it % 3;
            bool ex = tile >= ntiles;
            int ebase = (ex ? tile - ntiles : tile) * 64;
            const int* ix = ex ? idx2 : idx1;
            char* aHb = smem + OFF_A + s*A_STAGE;

            if (it >= 3) BAR_SYNC(4 + s, 512);         // wait empty

            int ge = ebase + el;
            if (ge < E) {
                int sidx = ix[ge], didx = ix[E + ge];
                const float* xs_ = X + (size_t)sidx * 12;
                const float* xd_ = X + (size_t)didx * 12;

                #pragma unroll
                for (int j = 0; j < 4; j++) {
                    int p = pu * 4 + j;
                    const float* xa = xs_ + c_EA[p] * 3;
                    const float* xb = xd_ + c_EB[p] * 3;
                    float dx = xa[0]-xb[0], dy = xa[1]-xb[1], dz = xa[2]-xb[2];
                    float D = sqrtf(dx*dx + dy*dy + dz*dz + 1e-6f);
                    float f[16];
                    #pragma unroll
                    for (int k = 0; k < 16; k++) {
                        float z = (D - (float)k * (20.f/15.f)) * 0.8f;
                        f[k] = __expf(-z * z);
                    }
                    uint32_t hw[8];
                    #pragma unroll
                    for (int k = 0; k < 8; k++)
                        hw[k] = pk2h(f[2*k], f[2*k+1]);
                    char* ah = aHb + el*ROWB + p*32;
                    *(uint4*)(ah)      = make_uint4(hw[0],hw[1],hw[2],hw[3]);
                    *(uint4*)(ah + 16) = make_uint4(hw[4],hw[5],hw[6],hw[7]);
                }

                if (pu == 3) {   // orientation features, cols 256..271
                    float ox = xs_[0], oy = xs_[1], oz = xs_[2];
                    const float* q = g_Q + (size_t)sidx * 9;
                    float q0=q[0],q1=q[1],q2=q[2],q3=q[3],q4=q[4],
                          q5=q[5],q6=q[6],q7=q[7],q8=q[8];
                    float fv[12];
                    #pragma unroll
                    for (int a = 0; a < 4; a++) {
                        int da = c_AMAP[a];
                        float px = xd_[da*3+0]-ox, py = xd_[da*3+1]-oy, pz = xd_[da*3+2]-oz;
                        float vx = q0*px + q3*py + q6*pz;
                        float vy = q1*px + q4*py + q7*pz;
                        float vz = q2*px + q5*py + q8*pz;
                        float n = sqrtf(vx*vx + vy*vy + vz*vz);
                        if (n == 0.f) n = 1.f;
                        float r = 1.f / n;
                        fv[a*3+0] = vx*r; fv[a*3+1] = vy*r; fv[a*3+2] = vz*r;
                    }
                    uint32_t hw[8];
                    #pragma unroll
                    for (int k = 0; k < 6; k++)
                        hw[k] = pk2h(fv[2*k], fv[2*k+1]);
                    hw[6] = hw[7] = 0u;
                    char* ah = aHb + el*ROWB + 512;
                    *(uint4*)(ah)      = make_uint4(hw[0],hw[1],hw[2],hw[3]);
                    *(uint4*)(ah + 16) = make_uint4(hw[4],hw[5],hw[6],hw[7]);
                }
            }
            BAR_SYNC(8, 256);        // drain producer STS (visibility)
            BAR_ARRIVE(1 + s, 512);  // signal full
        }
    }
}

// ------------------------------- launcher ----------------------------------
extern "C" void kernel_launch(void* const* d_in, const int* in_sizes, int n_in,
                              void* d_out, int out_size)
{
    const float* X   = (const float*)d_in[0];
    const int*   Ein = (const int*)d_in[1];
    const int*   Eex = (const int*)d_in[2];
    const float* nW  = (const float*)d_in[3];
    const float* nb  = (const float*)d_in[4];
    const float* eW  = (const float*)d_in[5];
    const float* eb  = (const float*)d_in[6];
    const float* gn  = (const float*)d_in[7];
    const float* bn  = (const float*)d_in[8];
    const float* ge  = (const float*)d_in[9];
    const float* be  = (const float*)d_in[10];

    int N = in_sizes[0] / 12;
    int E = in_sizes[1] / 2;
    float* out = (float*)d_out;

    cudaFuncSetAttribute(node_hmma_kernel, cudaFuncAttributeMaxDynamicSharedMemorySize,
                         NODE_SMEM);
    cudaFuncSetAttribute(edge_hmma_kernel, cudaFuncAttributeMaxDynamicSharedMemorySize,
                         EDGE_SMEM);

    int sms = 148;
    cudaDeviceGetAttribute(&sms, cudaDevAttrMultiProcessorCount, 0);

    q_kernel<<<(N + 127) / 128, 128>>>(X, N);
    node_hmma_kernel<<<sms * 2, 512, NODE_SMEM>>>(X, N, nW, nb, gn, bn, out);

    float* out_in = out + (size_t)N * 128;
    float* out_ex = out_in + (size_t)E * 128;
    edge_hmma_kernel<<<sms, 512, EDGE_SMEM>>>(X, Ein, Eex, E, eW, eb, ge, be,
                                              out_in, out_ex);
}